// round 13
// baseline (speedup 1.0000x reference)
#include <cuda_runtime.h>
#include <math.h>
#include <stdint.h>

#define DDIM 2048
#define NROWS 65536
#define WARPS_PB 8
#define NSTAGES 3
#define ROWS_PER_STAGE 8               // one row per warp per stage
#define STAGE_BYTES (ROWS_PER_STAGE * DDIM * 4)   // 65536
#define STAGE_UNITS (NROWS / ROWS_PER_STAGE)      // 8192 per side
#define MAX_CHUNKS 96                  // >= blocks per side for any SM count
#define GEMV_BLKS 128
#define COLS_PER_BLK (DDIM / GEMV_BLKS)  // 16
#define COMBINE_BLKS 64                // 32 col-tiles x 2 sides

// -------- device scratch (no allocations allowed) --------
__device__ float g_align[2][DDIM];
__device__ float g_acc[2][MAX_CHUNKS][DDIM];            // 1.5 MB
__device__ float g_m[2][MAX_CHUNKS];
__device__ float g_z[2][MAX_CHUNKS];
__device__ int   g_align_done;                          // 0 at rest
__device__ int   g_done;                                // 0 at rest
__device__ int   g_done2;                               // 0 at rest

// -------- PTX helpers --------
__device__ __forceinline__ uint32_t smem_u32(const void* p) {
    return (uint32_t)__cvta_generic_to_shared(p);
}
#define MBAR_INIT(addr, cnt) \
    asm volatile("mbarrier.init.shared.b64 [%0], %1;" :: "r"(addr), "r"(cnt) : "memory")
#define MBAR_EXPECT_TX(addr, bytes) \
    asm volatile("mbarrier.arrive.expect_tx.shared.b64 _, [%0], %1;" :: "r"(addr), "r"(bytes) : "memory")
#define BULK_G2S(dst, src, bytes, mbar) \
    asm volatile("cp.async.bulk.shared::cta.global.mbarrier::complete_tx::bytes [%0], [%1], %2, [%3];" \
                 :: "r"(dst), "l"(src), "r"(bytes), "r"(mbar) : "memory")
#define MBAR_WAIT_PARITY(addr, parity) do {                                        \
    uint32_t _m = (addr); uint32_t _p = (parity); uint32_t _done;                  \
    asm volatile("{\n\t.reg .pred p;\n\t"                                          \
        "mbarrier.try_wait.parity.acquire.cta.shared::cta.b64 p, [%1], %2;\n\t"    \
        "selp.b32 %0, 1, 0, p;\n\t}"                                               \
        : "=r"(_done) : "r"(_m), "r"(_p) : "memory");                              \
    if (!_done) {                                                                  \
        asm volatile("{\n\t.reg .pred P1;\n\t"                                     \
            "WL_%=:\n\t"                                                           \
            "mbarrier.try_wait.parity.acquire.cta.shared::cta.b64 P1, [%0], %1, 0x989680;\n\t" \
            "@P1 bra.uni WD_%=;\n\t"                                               \
            "bra.uni WL_%=;\n\t"                                                   \
            "WD_%=:\n\t}" :: "r"(_m), "r"(_p) : "memory");                         \
    }                                                                              \
} while (0)

// ---------------------------------------------------------
// ONE kernel: fused align GEMV + streaming attention + combine.
// Phase A: issue 3-stage TMA prologue (candidates stream from t=0).
// Phase B: blocks 0..127 compute the align GEMV cooperatively,
//          publish g_align + counter; all blocks poll (grid <= SM
//          count, 1 CTA/SM => all resident => no deadlock).
// Phase C: R8 streaming loop (measured optimum), one merge/block.
// Phase D: blocks 0..63 poll g_done == gridDim.x, then combine the
//          per-block partials (hot in L2) directly into out. Last
//          combine block resets the counters for graph replay.
// ---------------------------------------------------------
extern __shared__ float dynsmem[];     // NSTAGES * 64 KB ring; slot 0 reused for merge

__global__ void __launch_bounds__(256, 1)
attn_fused_all(const float* __restrict__ candL, const float* __restrict__ candR,
               const float* __restrict__ wl,    const float* __restrict__ wr,
               const float* __restrict__ Wa,    const float* __restrict__ ba,
               float* __restrict__ out) {
    const int H    = gridDim.x >> 1;
    const int side = (blockIdx.x >= H) ? 1 : 0;
    const int idx  = blockIdx.x - side * H;
    const float* cand = side ? candL : candR;
    const int tid  = threadIdx.x;
    const int warp = tid >> 5;
    const int lane = tid & 31;

    const int s0 = (int)(((long long)idx * STAGE_UNITS) / H);
    const int s1 = (int)(((long long)(idx + 1) * STAGE_UNITS) / H);
    const int ns = s1 - s0;            // ~110 stages

    __shared__ float  s_w[2][DDIM];    // 16 KB: word vectors for GEMV phase
    __shared__ float4 s_gl[64][4];     // 4 KB GEMV reduce (left)
    __shared__ float4 s_gr[64][4];     // 4 KB GEMV reduce (right)
    __shared__ float  s_m[WARPS_PB], s_z[WARPS_PB];
    __shared__ uint64_t s_mbar[NSTAGES];
    // combine-phase smem (reuses nothing live at that point)
    __shared__ float  s_mv[MAX_CHUNKS], s_zv[MAX_CHUNKS], s_coef[MAX_CHUNKS];
    __shared__ float4 s_part[16][16];

    if (tid == 0) {
#pragma unroll
        for (int s = 0; s < NSTAGES; s++)
            MBAR_INIT(smem_u32(&s_mbar[s]), 1);
    }
    __syncthreads();

    // ---- Phase A: TMA prologue first (no align dependency) ----
    if (tid == 0) {
        int pre = ns < NSTAGES ? ns : NSTAGES;
        for (int g = 0; g < pre; g++) {
            uint32_t mb = smem_u32(&s_mbar[g]);
            MBAR_EXPECT_TX(mb, STAGE_BYTES);
            BULK_G2S(smem_u32(dynsmem) + g * STAGE_BYTES,
                     cand + (size_t)(s0 + g) * ROWS_PER_STAGE * DDIM,
                     STAGE_BYTES, mb);
        }
    }

    // ---- Phase B: cooperative align GEMV (blocks 0..127) ----
    if (blockIdx.x < GEMV_BLKS) {
        for (int i = tid; i < DDIM; i += 256) {
            s_w[0][i] = wl[i];
            s_w[1][i] = wr[i];
        }
        __syncthreads();

        const int q  = tid & 3;        // float4 column within 16-col strip
        const int rg = tid >> 2;       // 64 row-groups of 32 rows
        const float4* Wp = reinterpret_cast<const float4*>(
            Wa + (size_t)(rg * 32) * DDIM + blockIdx.x * COLS_PER_BLK) + q;

        float4 accl = make_float4(0.f, 0.f, 0.f, 0.f);
        float4 accr = make_float4(0.f, 0.f, 0.f, 0.f);
        const int row0 = rg * 32;
#pragma unroll 8
        for (int r = 0; r < 32; r++) {
            float4 w = Wp[(size_t)r * (DDIM / 4)];
            float vl = s_w[0][row0 + r];
            float vr = s_w[1][row0 + r];
            accl.x = fmaf(vl, w.x, accl.x); accl.y = fmaf(vl, w.y, accl.y);
            accl.z = fmaf(vl, w.z, accl.z); accl.w = fmaf(vl, w.w, accl.w);
            accr.x = fmaf(vr, w.x, accr.x); accr.y = fmaf(vr, w.y, accr.y);
            accr.z = fmaf(vr, w.z, accr.z); accr.w = fmaf(vr, w.w, accr.w);
        }
        s_gl[rg][q] = accl;
        s_gr[rg][q] = accr;
        __syncthreads();

#pragma unroll
        for (int o = 32; o > 0; o >>= 1) {
            if (rg < o) {
                float4 a = s_gl[rg][q], b4 = s_gl[rg + o][q];
                a.x += b4.x; a.y += b4.y; a.z += b4.z; a.w += b4.w;
                s_gl[rg][q] = a;
                float4 c = s_gr[rg][q], d4 = s_gr[rg + o][q];
                c.x += d4.x; c.y += d4.y; c.z += d4.z; c.w += d4.w;
                s_gr[rg][q] = c;
            }
            __syncthreads();
        }

        if (tid < COLS_PER_BLK) {
            int j = blockIdx.x * COLS_PER_BLK + tid;
            float bias = ba[j];
            const float* pl = reinterpret_cast<const float*>(&s_gl[0][0]);
            const float* pr = reinterpret_cast<const float*>(&s_gr[0][0]);
            g_align[0][j] = tanhf(pl[tid] + bias);
            g_align[1][j] = tanhf(pr[tid] + bias);
        }
        __threadfence();
        __syncthreads();
        if (tid == 0) atomicAdd(&g_align_done, 1);
    }

    // ---- all blocks wait for align publication ----
    if (tid == 0) {
        while (atomicAdd(&g_align_done, 0) < GEMV_BLKS) __nanosleep(128);
    }
    __syncthreads();
    __threadfence();                   // acquire side of the flag protocol

    // align slice in registers: lane l owns cols {4l + 128c} (L2-broadcast)
    float4 al[16];
    {
        const float4* ap = reinterpret_cast<const float4*>(&g_align[side][0]) + lane;
#pragma unroll
        for (int c = 0; c < 16; c++) al[c] = ap[c * 32];
    }

    // ---- Phase C: main streaming loop (R8 verbatim) ----
    float4 acc[16];
#pragma unroll
    for (int c = 0; c < 16; c++) acc[c] = make_float4(0.f, 0.f, 0.f, 0.f);
    float m = -1e30f, Z = 0.f;

    for (int g = 0; g < ns; g++) {
        const int slot = g % NSTAGES;
        MBAR_WAIT_PARITY(smem_u32(&s_mbar[slot]), (g / NSTAGES) & 1);

        const float4* rp = reinterpret_cast<const float4*>(
            dynsmem + slot * (STAGE_BYTES / 4) + warp * DDIM) + lane;

        float4 x[16];
#pragma unroll
        for (int c = 0; c < 16; c++) x[c] = rp[c * 32];

        float p0 = 0.f, p1 = 0.f, p2 = 0.f, p3 = 0.f;
#pragma unroll
        for (int c = 0; c < 16; c++) {
            p0 = fmaf(x[c].x, al[c].x, p0);
            p1 = fmaf(x[c].y, al[c].y, p1);
            p2 = fmaf(x[c].z, al[c].z, p2);
            p3 = fmaf(x[c].w, al[c].w, p3);
        }
        float p = (p0 + p1) + (p2 + p3);
#pragma unroll
        for (int o = 16; o > 0; o >>= 1)
            p += __shfl_xor_sync(0xffffffffu, p, o);

        if (p > m) {
            float c = __expf(m - p);   // first row: exp(-huge) == 0
            Z *= c;
#pragma unroll
            for (int k = 0; k < 16; k++) {
                acc[k].x *= c; acc[k].y *= c; acc[k].z *= c; acc[k].w *= c;
            }
            m = p;
        }
        float w = __expf(p - m);
        Z += w;
#pragma unroll
        for (int k = 0; k < 16; k++) {
            acc[k].x = fmaf(w, x[k].x, acc[k].x);
            acc[k].y = fmaf(w, x[k].y, acc[k].y);
            acc[k].z = fmaf(w, x[k].z, acc[k].z);
            acc[k].w = fmaf(w, x[k].w, acc[k].w);
        }

        __syncthreads();               // all warps done with this slot
        if (tid == 0 && g + NSTAGES < ns) {
            uint32_t mb = smem_u32(&s_mbar[slot]);
            MBAR_EXPECT_TX(mb, STAGE_BYTES);
            BULK_G2S(smem_u32(dynsmem) + slot * STAGE_BYTES,
                     cand + (size_t)(s0 + g + NSTAGES) * ROWS_PER_STAGE * DDIM,
                     STAGE_BYTES, mb);
        }
    }

    // ---- ONE block-level merge of the 8 warp states ----
    if (lane == 0) { s_m[warp] = m; s_z[warp] = Z; }
    __syncthreads();

    float mb2 = s_m[0];
#pragma unroll
    for (int w = 1; w < WARPS_PB; w++) mb2 = fmaxf(mb2, s_m[w]);
    float scale = __expf(m - mb2);     // warp-uniform

    float* s_acc = dynsmem;            // 64 KB merge buffer (ring slot 0)
    float4* sa = reinterpret_cast<float4*>(s_acc + warp * DDIM) + lane;
#pragma unroll
    for (int c = 0; c < 16; c++) {
        float4 v = acc[c];
        v.x *= scale; v.y *= scale; v.z *= scale; v.w *= scale;
        sa[c * 32] = v;
    }
    __syncthreads();

    for (int j = tid; j < DDIM; j += 256) {
        float ssum = 0.f;
#pragma unroll
        for (int w = 0; w < WARPS_PB; w++) ssum += s_acc[w * DDIM + j];
        g_acc[side][idx][j] = ssum;
    }
    if (tid == 0) {
        float zb = 0.f;
#pragma unroll
        for (int w = 0; w < WARPS_PB; w++)
            zb += s_z[w] * __expf(s_m[w] - mb2);
        g_m[side][idx] = mb2;
        g_z[side][idx] = zb;
    }

    // ---- publish this block's partial ----
    __threadfence();
    __syncthreads();
    if (tid == 0) atomicAdd(&g_done, 1);

    // ---- Phase D: combine (blocks 0..63 only) ----
    if (blockIdx.x >= COMBINE_BLKS) return;

    if (tid == 0) {
        while (atomicAdd(&g_done, 0) < (int)gridDim.x) __nanosleep(128);
    }
    __syncthreads();
    __threadfence();                   // acquire: g_acc/g_m/g_z visible

    const int cside = blockIdx.x >> 5;           // 0..1
    const int ctile = blockIdx.x & 31;           // 0..31 (64-col tiles)
    const int f4   = tid & 15;
    const int part = tid >> 4;

    if (tid < H) { s_mv[tid] = g_m[cside][tid]; s_zv[tid] = g_z[cside][tid]; }
    __syncthreads();

    float M = -1e30f;
    for (int c = 0; c < H; c++) M = fmaxf(M, s_mv[c]);
    float Zt = 0.f;
    for (int c = 0; c < H; c++) Zt += s_zv[c] * __expf(s_mv[c] - M);
    float Zi = 1.0f / Zt;
    if (tid < H) s_coef[tid] = __expf(s_mv[tid] - M) * Zi;
    __syncthreads();

    const int col4 = ctile * 16 + f4;            // float4 col in [0,512)
    const float4* ap = reinterpret_cast<const float4*>(&g_acc[cside][0][0]) + col4;

    float4 s = make_float4(0.f, 0.f, 0.f, 0.f);
    for (int c = part; c < H; c += 16) {
        float4 v = ap[(size_t)c * (DDIM / 4)];
        float k = s_coef[c];
        s.x = fmaf(k, v.x, s.x);
        s.y = fmaf(k, v.y, s.y);
        s.z = fmaf(k, v.z, s.z);
        s.w = fmaf(k, v.w, s.w);
    }
    s_part[part][f4] = s;
    __syncthreads();

#pragma unroll
    for (int o = 8; o > 0; o >>= 1) {
        if (part < o) {
            float4 a = s_part[part][f4];
            float4 bb = s_part[part + o][f4];
            a.x += bb.x; a.y += bb.y; a.z += bb.z; a.w += bb.w;
            s_part[part][f4] = a;
        }
        __syncthreads();
    }

    if (part == 0)
        reinterpret_cast<float4*>(out)[cside * (DDIM / 4) + col4] = s_part[0][f4];

    // ---- counter reset for graph replay (last combine block) ----
    __syncthreads();
    if (tid == 0) {
        int v = atomicAdd(&g_done2, 1);
        if (v == COMBINE_BLKS - 1) {   // everyone else is past all polls
            g_done = 0;
            g_align_done = 0;
            g_done2 = 0;
            __threadfence();
        }
    }
}

// ---------------------------------------------------------
extern "C" void kernel_launch(void* const* d_in, const int* in_sizes, int n_in,
                              void* d_out, int out_size) {
    const float* wl    = (const float*)d_in[0];  // embed_word_l  [1, D]
    const float* wr    = (const float*)d_in[1];  // embed_word_r  [1, D]
    const float* candL = (const float*)d_in[2];  // embed_candidates_l [N, D]
    const float* candR = (const float*)d_in[3];  // embed_candidates_r [N, D]
    const float* Wa    = (const float*)d_in[4];  // W_a [D, D]
    const float* ba    = (const float*)d_in[5];  // b_a [1, D]
    float* out = (float*)d_out;

    static int grid_attn = 0;          // set once; deterministic per device
    if (!grid_attn) {
        int sm = 0;
        cudaDeviceGetAttribute(&sm, cudaDevAttrMultiProcessorCount, 0);
        if (sm <= 0) sm = 148;
        grid_attn = sm & ~1;           // even: half per side; <= SM count (all resident)
        if (grid_attn > 2 * MAX_CHUNKS) grid_attn = 2 * MAX_CHUNKS;
        cudaFuncSetAttribute(attn_fused_all,
                             cudaFuncAttributeMaxDynamicSharedMemorySize,
                             NSTAGES * STAGE_BYTES);
    }

    attn_fused_all<<<grid_attn, 256, NSTAGES * STAGE_BYTES>>>(
        candL, candR, wl, wr, Wa, ba, out);
}

// round 14
// speedup vs baseline: 1.0301x; 1.0301x over previous
#include <cuda_runtime.h>
#include <math.h>
#include <stdint.h>

#define DDIM 2048
#define NROWS 65536
#define WARPS_PB 8
#define NSTAGES 3
#define ROWS_PER_STAGE 8               // one row per warp per stage
#define STAGE_BYTES (ROWS_PER_STAGE * DDIM * 4)   // 65536
#define STAGE_UNITS (NROWS / ROWS_PER_STAGE)      // 8192 per side
#define MAX_CHUNKS 96                  // >= blocks per side for any SM count
#define GEMV_BLKS 128
#define COLS_PER_BLK (DDIM / GEMV_BLKS)  // 16

// -------- device scratch (no allocations allowed) --------
__device__ float g_align[2][DDIM];
__device__ float g_acc[2][MAX_CHUNKS][DDIM];            // 1.5 MB
__device__ float g_m[2][MAX_CHUNKS];
__device__ float g_z[2][MAX_CHUNKS];
__device__ int   g_align_done;                          // 0 at rest; reset by combine_all

// -------- PTX helpers --------
__device__ __forceinline__ uint32_t smem_u32(const void* p) {
    return (uint32_t)__cvta_generic_to_shared(p);
}
#define MBAR_INIT(addr, cnt) \
    asm volatile("mbarrier.init.shared.b64 [%0], %1;" :: "r"(addr), "r"(cnt) : "memory")
#define MBAR_EXPECT_TX(addr, bytes) \
    asm volatile("mbarrier.arrive.expect_tx.shared.b64 _, [%0], %1;" :: "r"(addr), "r"(bytes) : "memory")
#define BULK_G2S(dst, src, bytes, mbar) \
    asm volatile("cp.async.bulk.shared::cta.global.mbarrier::complete_tx::bytes [%0], [%1], %2, [%3];" \
                 :: "r"(dst), "l"(src), "r"(bytes), "r"(mbar) : "memory")
#define MBAR_WAIT_PARITY(addr, parity) do {                                        \
    uint32_t _m = (addr); uint32_t _p = (parity); uint32_t _done;                  \
    asm volatile("{\n\t.reg .pred p;\n\t"                                          \
        "mbarrier.try_wait.parity.acquire.cta.shared::cta.b64 p, [%1], %2;\n\t"    \
        "selp.b32 %0, 1, 0, p;\n\t}"                                               \
        : "=r"(_done) : "r"(_m), "r"(_p) : "memory");                              \
    if (!_done) {                                                                  \
        asm volatile("{\n\t.reg .pred P1;\n\t"                                     \
            "WL_%=:\n\t"                                                           \
            "mbarrier.try_wait.parity.acquire.cta.shared::cta.b64 P1, [%0], %1, 0x989680;\n\t" \
            "@P1 bra.uni WD_%=;\n\t"                                               \
            "bra.uni WL_%=;\n\t"                                                   \
            "WD_%=:\n\t}" :: "r"(_m), "r"(_p) : "memory");                         \
    }                                                                              \
} while (0)

// ---------------------------------------------------------
// Kernel 1: LONG-STREAM attention with FUSED align GEMV.
// Phase A: issue 3-stage TMA prologue (candidates stream from t=0,
//          independent of align).
// Phase B: blocks 0..127 compute 16 GEMV columns each (float4
//          strip loads, ~1.5us), publish g_align + counter; ALL
//          blocks poll the counter (grid <= SM count, 1 CTA/SM =>
//          all resident => no deadlock), then read al[] from L2.
// Phase C: streaming loop with EARLY slot release — the barrier
//          and refetch sit right after the x[] register loads, so
//          the TMA refetch overlaps the dot/softmax/accumulate
//          compute of the current stage (~600 cyc more lead).
// ---------------------------------------------------------
extern __shared__ float dynsmem[];     // NSTAGES * 64 KB ring; slot 0 reused for merge

__global__ void __launch_bounds__(256, 1)
attn_stream(const float* __restrict__ candL, const float* __restrict__ candR,
            const float* __restrict__ wl,    const float* __restrict__ wr,
            const float* __restrict__ Wa,    const float* __restrict__ ba) {
    const int H    = gridDim.x >> 1;
    const int side = (blockIdx.x >= H) ? 1 : 0;
    const int idx  = blockIdx.x - side * H;
    const float* cand = side ? candL : candR;
    const int tid  = threadIdx.x;
    const int warp = tid >> 5;
    const int lane = tid & 31;

    const int s0 = (int)(((long long)idx * STAGE_UNITS) / H);
    const int s1 = (int)(((long long)(idx + 1) * STAGE_UNITS) / H);
    const int ns = s1 - s0;            // ~108 stages

    __shared__ float  s_w[2][DDIM];    // 16 KB: word vectors for GEMV phase
    __shared__ float4 s_gl[64][4];     // 4 KB GEMV reduce (left)
    __shared__ float4 s_gr[64][4];     // 4 KB GEMV reduce (right)
    __shared__ float  s_m[WARPS_PB], s_z[WARPS_PB];
    __shared__ uint64_t s_mbar[NSTAGES];

    if (tid == 0) {
#pragma unroll
        for (int s = 0; s < NSTAGES; s++)
            MBAR_INIT(smem_u32(&s_mbar[s]), 1);
    }
    __syncthreads();

    // ---- Phase A: TMA prologue first (no align dependency) ----
    if (tid == 0) {
        int pre = ns < NSTAGES ? ns : NSTAGES;
        for (int g = 0; g < pre; g++) {
            uint32_t mb = smem_u32(&s_mbar[g]);
            MBAR_EXPECT_TX(mb, STAGE_BYTES);
            BULK_G2S(smem_u32(dynsmem) + g * STAGE_BYTES,
                     cand + (size_t)(s0 + g) * ROWS_PER_STAGE * DDIM,
                     STAGE_BYTES, mb);
        }
    }

    // ---- Phase B: cooperative align GEMV (blocks 0..127) ----
    if (blockIdx.x < GEMV_BLKS) {
        for (int i = tid; i < DDIM; i += 256) {
            s_w[0][i] = wl[i];
            s_w[1][i] = wr[i];
        }
        __syncthreads();

        const int q  = tid & 3;        // float4 column within 16-col strip
        const int rg = tid >> 2;       // 64 row-groups of 32 rows
        const float4* Wp = reinterpret_cast<const float4*>(
            Wa + (size_t)(rg * 32) * DDIM + blockIdx.x * COLS_PER_BLK) + q;

        float4 accl = make_float4(0.f, 0.f, 0.f, 0.f);
        float4 accr = make_float4(0.f, 0.f, 0.f, 0.f);
        const int row0 = rg * 32;
#pragma unroll 8
        for (int r = 0; r < 32; r++) {
            float4 w = Wp[(size_t)r * (DDIM / 4)];
            float vl = s_w[0][row0 + r];
            float vr = s_w[1][row0 + r];
            accl.x = fmaf(vl, w.x, accl.x); accl.y = fmaf(vl, w.y, accl.y);
            accl.z = fmaf(vl, w.z, accl.z); accl.w = fmaf(vl, w.w, accl.w);
            accr.x = fmaf(vr, w.x, accr.x); accr.y = fmaf(vr, w.y, accr.y);
            accr.z = fmaf(vr, w.z, accr.z); accr.w = fmaf(vr, w.w, accr.w);
        }
        s_gl[rg][q] = accl;
        s_gr[rg][q] = accr;
        __syncthreads();

#pragma unroll
        for (int o = 32; o > 0; o >>= 1) {
            if (rg < o) {
                float4 a = s_gl[rg][q], b4 = s_gl[rg + o][q];
                a.x += b4.x; a.y += b4.y; a.z += b4.z; a.w += b4.w;
                s_gl[rg][q] = a;
                float4 c = s_gr[rg][q], d4 = s_gr[rg + o][q];
                c.x += d4.x; c.y += d4.y; c.z += d4.z; c.w += d4.w;
                s_gr[rg][q] = c;
            }
            __syncthreads();
        }

        if (tid < COLS_PER_BLK) {
            int j = blockIdx.x * COLS_PER_BLK + tid;
            float bias = ba[j];
            const float* pl = reinterpret_cast<const float*>(&s_gl[0][0]);
            const float* pr = reinterpret_cast<const float*>(&s_gr[0][0]);
            g_align[0][j] = tanhf(pl[tid] + bias);
            g_align[1][j] = tanhf(pr[tid] + bias);
        }
        __threadfence();
        __syncthreads();
        if (tid == 0) atomicAdd(&g_align_done, 1);
    }

    // ---- all blocks wait for align publication ----
    if (tid == 0) {
        while (atomicAdd(&g_align_done, 0) < GEMV_BLKS) __nanosleep(128);
    }
    __syncthreads();
    __threadfence();                   // acquire side of the flag protocol

    // align slice in registers: lane l owns cols {4l + 128c} (L2-broadcast)
    float4 al[16];
    {
        const float4* ap = reinterpret_cast<const float4*>(&g_align[side][0]) + lane;
#pragma unroll
        for (int c = 0; c < 16; c++) al[c] = ap[c * 32];
    }

    // ---- Phase C: main streaming loop, EARLY slot release ----
    float4 acc[16];
#pragma unroll
    for (int c = 0; c < 16; c++) acc[c] = make_float4(0.f, 0.f, 0.f, 0.f);
    float m = -1e30f, Z = 0.f;

    for (int g = 0; g < ns; g++) {
        const int slot = g % NSTAGES;
        MBAR_WAIT_PARITY(smem_u32(&s_mbar[slot]), (g / NSTAGES) & 1);

        const float4* rp = reinterpret_cast<const float4*>(
            dynsmem + slot * (STAGE_BYTES / 4) + warp * DDIM) + lane;

        float4 x[16];
#pragma unroll
        for (int c = 0; c < 16; c++) x[c] = rp[c * 32];

        // slot fully read into registers by every warp -> release it NOW,
        // so the refetch overlaps the compute below.
        __syncthreads();
        if (tid == 0 && g + NSTAGES < ns) {
            uint32_t mb = smem_u32(&s_mbar[slot]);
            MBAR_EXPECT_TX(mb, STAGE_BYTES);
            BULK_G2S(smem_u32(dynsmem) + slot * STAGE_BYTES,
                     cand + (size_t)(s0 + g + NSTAGES) * ROWS_PER_STAGE * DDIM,
                     STAGE_BYTES, mb);
        }

        float p0 = 0.f, p1 = 0.f, p2 = 0.f, p3 = 0.f;
#pragma unroll
        for (int c = 0; c < 16; c++) {
            p0 = fmaf(x[c].x, al[c].x, p0);
            p1 = fmaf(x[c].y, al[c].y, p1);
            p2 = fmaf(x[c].z, al[c].z, p2);
            p3 = fmaf(x[c].w, al[c].w, p3);
        }
        float p = (p0 + p1) + (p2 + p3);
#pragma unroll
        for (int o = 16; o > 0; o >>= 1)
            p += __shfl_xor_sync(0xffffffffu, p, o);

        if (p > m) {
            float c = __expf(m - p);   // first row: exp(-huge) == 0
            Z *= c;
#pragma unroll
            for (int k = 0; k < 16; k++) {
                acc[k].x *= c; acc[k].y *= c; acc[k].z *= c; acc[k].w *= c;
            }
            m = p;
        }
        float w = __expf(p - m);
        Z += w;
#pragma unroll
        for (int k = 0; k < 16; k++) {
            acc[k].x = fmaf(w, x[k].x, acc[k].x);
            acc[k].y = fmaf(w, x[k].y, acc[k].y);
            acc[k].z = fmaf(w, x[k].z, acc[k].z);
            acc[k].w = fmaf(w, x[k].w, acc[k].w);
        }
    }

    // ---- ONE block-level merge of the 8 warp states ----
    if (lane == 0) { s_m[warp] = m; s_z[warp] = Z; }
    __syncthreads();

    float mb2 = s_m[0];
#pragma unroll
    for (int w = 1; w < WARPS_PB; w++) mb2 = fmaxf(mb2, s_m[w]);
    float scale = __expf(m - mb2);     // warp-uniform

    float* s_acc = dynsmem;            // 64 KB merge buffer (ring slot 0)
    float4* sa = reinterpret_cast<float4*>(s_acc + warp * DDIM) + lane;
#pragma unroll
    for (int c = 0; c < 16; c++) {
        float4 v = acc[c];
        v.x *= scale; v.y *= scale; v.z *= scale; v.w *= scale;
        sa[c * 32] = v;
    }
    __syncthreads();

    for (int j = tid; j < DDIM; j += 256) {
        float ssum = 0.f;
#pragma unroll
        for (int w = 0; w < WARPS_PB; w++) ssum += s_acc[w * DDIM + j];
        g_acc[side][idx][j] = ssum;
    }
    if (tid == 0) {
        float zb = 0.f;
#pragma unroll
        for (int w = 0; w < WARPS_PB; w++)
            zb += s_z[w] * __expf(s_m[w] - mb2);
        g_m[side][idx] = mb2;
        g_z[side][idx] = zb;
    }
}

// ---------------------------------------------------------
// Kernel 2: single tail kernel. grid (32, 2), 256 threads.
// Also RESETS g_align_done for the next invocation (runs strictly
// after attn_stream; keeps kernel_launch replay-deterministic).
// out layout: [0..2047] = left result, [2048..4095] = right.
// ---------------------------------------------------------
__global__ void __launch_bounds__(256, 4)
combine_all(float* __restrict__ out, int H) {
    if (blockIdx.x == 0 && blockIdx.y == 0 && threadIdx.x == 0)
        g_align_done = 0;

    const int side = blockIdx.y;
    const int t    = threadIdx.x;
    const int f4   = t & 15;           // float4 column within 64-col tile
    const int part = t >> 4;           // 0..15

    __shared__ float s_mv[MAX_CHUNKS];
    __shared__ float s_zv[MAX_CHUNKS];
    __shared__ float s_coef[MAX_CHUNKS];
    __shared__ float4 s_part[16][16];

    if (t < H) { s_mv[t] = g_m[side][t]; s_zv[t] = g_z[side][t]; }
    __syncthreads();

    float M = -1e30f;
    for (int c = 0; c < H; c++) M = fmaxf(M, s_mv[c]);
    float Zt = 0.f;
    for (int c = 0; c < H; c++) Zt += s_zv[c] * __expf(s_mv[c] - M);
    float Zi = 1.0f / Zt;
    if (t < H) s_coef[t] = __expf(s_mv[t] - M) * Zi;
    __syncthreads();

    const int col4 = blockIdx.x * 16 + f4;          // float4 col in [0,512)
    const float4* ap = reinterpret_cast<const float4*>(&g_acc[side][0][0]) + col4;

    float4 s = make_float4(0.f, 0.f, 0.f, 0.f);
    for (int c = part; c < H; c += 16) {
        float4 v = ap[(size_t)c * (DDIM / 4)];
        float k = s_coef[c];
        s.x = fmaf(k, v.x, s.x);
        s.y = fmaf(k, v.y, s.y);
        s.z = fmaf(k, v.z, s.z);
        s.w = fmaf(k, v.w, s.w);
    }
    s_part[part][f4] = s;
    __syncthreads();

#pragma unroll
    for (int o = 8; o > 0; o >>= 1) {
        if (part < o) {
            float4 a = s_part[part][f4];
            float4 bb = s_part[part + o][f4];
            a.x += bb.x; a.y += bb.y; a.z += bb.z; a.w += bb.w;
            s_part[part][f4] = a;
        }
        __syncthreads();
    }

    if (part == 0)
        reinterpret_cast<float4*>(out)[side * (DDIM / 4) + col4] = s_part[0][f4];
}

// ---------------------------------------------------------
extern "C" void kernel_launch(void* const* d_in, const int* in_sizes, int n_in,
                              void* d_out, int out_size) {
    const float* wl    = (const float*)d_in[0];  // embed_word_l  [1, D]
    const float* wr    = (const float*)d_in[1];  // embed_word_r  [1, D]
    const float* candL = (const float*)d_in[2];  // embed_candidates_l [N, D]
    const float* candR = (const float*)d_in[3];  // embed_candidates_r [N, D]
    const float* Wa    = (const float*)d_in[4];  // W_a [D, D]
    const float* ba    = (const float*)d_in[5];  // b_a [1, D]
    float* out = (float*)d_out;

    static int grid_attn = 0;          // set once; deterministic per device
    if (!grid_attn) {
        int sm = 0;
        cudaDeviceGetAttribute(&sm, cudaDevAttrMultiProcessorCount, 0);
        if (sm <= 0) sm = 148;
        grid_attn = sm & ~1;           // even: half per side; <= SM count (all resident)
        if (grid_attn > 2 * MAX_CHUNKS) grid_attn = 2 * MAX_CHUNKS;
        cudaFuncSetAttribute(attn_stream,
                             cudaFuncAttributeMaxDynamicSharedMemorySize,
                             NSTAGES * STAGE_BYTES);
    }
    const int H = grid_attn / 2;

    attn_stream<<<grid_attn, 256, NSTAGES * STAGE_BYTES>>>(candL, candR, wl, wr, Wa, ba);
    combine_all<<<dim3(DDIM / 64, 2), 256>>>(out, H);
}